// round 5
// baseline (speedup 1.0000x reference)
#include <cuda_runtime.h>

// Quantum multi-encoding conv + MLP, fused single kernel.
// One thread per batch element; 16-amp complex state held in registers.

struct U2 {
    float r00, i00, r01, i01, r10, i10, r11, i11;
};

// U = Rz(a4) Ry(a3) Rz(a2) Ry(a1) Rz(a0) H
__device__ __forceinline__ U2 buildU5(float a0, float a1, float a2, float a3, float a4) {
    const float rh = 0.70710678118654752f;
    float c, s;
    // Rz(a0) * H:
    // row0 = e^{-i a0/2} * rh * (1, 1), row1 = e^{+i a0/2} * rh * (1, -1)
    __sincosf(0.5f * a0, &s, &c);
    float u00r = rh * c, u00i = -rh * s;
    float u01r = u00r,   u01i = u00i;
    float u10r = rh * c, u10i = rh * s;
    float u11r = -u10r,  u11i = -u10i;
    // Ry(a1): row0' = c*row0 - s*row1 ; row1' = s*row0 + c*row1
    __sincosf(0.5f * a1, &s, &c);
    float n00r = c*u00r - s*u10r, n00i = c*u00i - s*u10i;
    float n01r = c*u01r - s*u11r, n01i = c*u01i - s*u11i;
    float n10r = s*u00r + c*u10r, n10i = s*u00i + c*u10i;
    float n11r = s*u01r + c*u11r, n11i = s*u01i + c*u11i;
    // Rz(a2): row0 *= e^{-i a2/2} => (cx+sy, cy-sx); row1 *= e^{+i a2/2} => (cx-sy, cy+sx)
    __sincosf(0.5f * a2, &s, &c);
    u00r = c*n00r + s*n00i; u00i = c*n00i - s*n00r;
    u01r = c*n01r + s*n01i; u01i = c*n01i - s*n01r;
    u10r = c*n10r - s*n10i; u10i = c*n10i + s*n10r;
    u11r = c*n11r - s*n11i; u11i = c*n11i + s*n11r;
    // Ry(a3)
    __sincosf(0.5f * a3, &s, &c);
    n00r = c*u00r - s*u10r; n00i = c*u00i - s*u10i;
    n01r = c*u01r - s*u11r; n01i = c*u01i - s*u11i;
    n10r = s*u00r + c*u10r; n10i = s*u00i + c*u10i;
    n11r = s*u01r + c*u11r; n11i = s*u01i + c*u11i;
    // Rz(a4)
    __sincosf(0.5f * a4, &s, &c);
    U2 u;
    u.r00 = c*n00r + s*n00i; u.i00 = c*n00i - s*n00r;
    u.r01 = c*n01r + s*n01i; u.i01 = c*n01i - s*n01r;
    u.r10 = c*n10r - s*n10i; u.i10 = c*n10i + s*n10r;
    u.r11 = c*n11r - s*n11i; u.i11 = c*n11i + s*n11r;
    return u;
}

template<int MASK>
__device__ __forceinline__ void applyU(float sr[16], float si[16], const U2& u) {
#pragma unroll
    for (int p = 0; p < 16; p++) {
        if (p & MASK) continue;
        const int q = p | MASK;
        float ar = sr[p], ai = si[p], br = sr[q], bi = si[q];
        sr[p] = u.r00*ar - u.i00*ai + u.r01*br - u.i01*bi;
        si[p] = u.r00*ai + u.i00*ar + u.r01*bi + u.i01*br;
        sr[q] = u.r10*ar - u.i10*ai + u.r11*br - u.i11*bi;
        si[q] = u.r10*ai + u.i10*ar + u.r11*bi + u.i11*br;
    }
}

// Specialized last-qubit gate: U = Rz(a)*H, where u01=u00, u11=-u10.
// out_p = u00*(a+b), out_q = u10*(a-b).  12 fma-ops/pair vs 16.
__device__ __forceinline__ void applyUH1(float sr[16], float si[16], float a0) {
    const float rh = 0.70710678118654752f;
    float c, s;
    __sincosf(0.5f * a0, &s, &c);
    const float u0r = rh * c, u0i = -rh * s;   // u00
    const float u1r = rh * c, u1i =  rh * s;   // u10
#pragma unroll
    for (int p = 0; p < 16; p += 2) {
        const int q = p | 1;
        float sumr = sr[p] + sr[q], sumi = si[p] + si[q];
        float difr = sr[p] - sr[q], difi = si[p] - si[q];
        sr[p] = u0r*sumr - u0i*sumi;
        si[p] = u0r*sumi + u0i*sumr;
        sr[q] = u1r*difr - u1i*difi;
        si[q] = u1r*difi + u1i*difr;
    }
}

template<int MASK>
__device__ __forceinline__ void applyRyFixed(float sr[16], float si[16], float c, float s) {
#pragma unroll
    for (int p = 0; p < 16; p++) {
        if (p & MASK) continue;
        const int q = p | MASK;
        float ar = sr[p], br = sr[q];
        sr[p] = c*ar - s*br;
        sr[q] = s*ar + c*br;
        float ai = si[p], bi = si[q];
        si[p] = c*ai - s*bi;
        si[q] = s*ai + c*bi;
    }
}

__global__ void __launch_bounds__(64)
multi_encoding_kernel(const float* __restrict__ x,
                      const float* __restrict__ crz_theta,
                      const float* __restrict__ ry_theta,
                      const float* __restrict__ fc1_w,
                      const float* __restrict__ fc1_b,
                      const float* __restrict__ fc2_w,
                      const float* __restrict__ fc2_b,
                      float* __restrict__ out,
                      int nB)
{
    int b = blockIdx.x * blockDim.x + threadIdx.x;
    if (b >= nB) return;
    const float* img = x + b * 784;

    // ---- fixed per-run constants (computed once per thread, precise) ----
    // CRZ diagonal: exp(+0.5i * theta * S_b), S_b from bit pattern.
    float thc = 0.5f * crz_theta[0];
    float dr[16], di[16];
#pragma unroll
    for (int bb = 0; bb < 16; bb++) {
        const int b3 = (bb >> 3) & 1, b2_ = (bb >> 2) & 1, b1_ = (bb >> 1) & 1, b0 = bb & 1;
        const int S = b3*(2*b2_-1) + b2_*(2*b1_-1) + b1_*(2*b0-1) + b0*(2*b3-1);
        float ang = thc * (float)S;
        dr[bb] = cosf(ang);
        di[bb] = sinf(ang);
    }
    float rc, rs;
    {
        float a = 0.5f * ry_theta[0];
        rc = cosf(a);
        rs = sinf(a);
    }

    // ---- state |0000> ----
    float sr[16], si[16];
#pragma unroll
    for (int k = 0; k < 16; k++) { sr[k] = 0.f; si[k] = 0.f; }
    sr[0] = 1.f;

    // ---- fc1 accumulators ----
    float h1[20];
#pragma unroll
    for (int o = 0; o < 20; o++) h1[o] = 0.f;

    int win = 0;
    for (int iw = 0; iw < 14; iw++) {
        const float* rp = img + (iw * 2) * 28;
        for (int jw = 0; jw < 14; jw++, win++) {
            const int j = jw * 2;
            float f[16];
            // NOTE: truncated edge windows are COMPACTED row-major over h*w
            // then zero-padded (matches reference _window_idx), not masked.
            if (iw < 13 && jw < 13) {            // h=4, w=4
#pragma unroll
                for (int r = 0; r < 4; r++) {
                    float2 A = *reinterpret_cast<const float2*>(rp + r * 28 + j);
                    float2 B = *reinterpret_cast<const float2*>(rp + r * 28 + j + 2);
                    f[r*4+0] = A.x; f[r*4+1] = A.y; f[r*4+2] = B.x; f[r*4+3] = B.y;
                }
            } else if (jw < 13) {                 // iw==13: h=2, w=4
#pragma unroll
                for (int r = 0; r < 2; r++) {
                    float2 A = *reinterpret_cast<const float2*>(rp + r * 28 + j);
                    float2 B = *reinterpret_cast<const float2*>(rp + r * 28 + j + 2);
                    f[r*4+0] = A.x; f[r*4+1] = A.y; f[r*4+2] = B.x; f[r*4+3] = B.y;
                }
#pragma unroll
                for (int k = 8; k < 16; k++) f[k] = 0.f;
            } else if (iw < 13) {                 // jw==13: h=4, w=2 (compacted!)
#pragma unroll
                for (int r = 0; r < 4; r++) {
                    float2 A = *reinterpret_cast<const float2*>(rp + r * 28 + j);
                    f[r*2+0] = A.x; f[r*2+1] = A.y;
                }
#pragma unroll
                for (int k = 8; k < 16; k++) f[k] = 0.f;
            } else {                              // corner: h=2, w=2
                float2 A = *reinterpret_cast<const float2*>(rp + j);
                float2 B = *reinterpret_cast<const float2*>(rp + 28 + j);
                f[0] = A.x; f[1] = A.y; f[2] = B.x; f[3] = B.y;
#pragma unroll
                for (int k = 4; k < 16; k++) f[k] = 0.f;
            }

            // qubit w occupies bit (3-w): masks 8,4,2,1
            {
                U2 u = buildU5(f[0], f[1], f[2], f[3], f[4]);
                applyU<8>(sr, si, u);
            }
            {
                U2 u = buildU5(f[5], f[6], f[7], f[8], f[9]);
                applyU<4>(sr, si, u);
            }
            {
                U2 u = buildU5(f[10], f[11], f[12], f[13], f[14]);
                applyU<2>(sr, si, u);
            }
            applyUH1(sr, si, f[15]);

            // CRZ diagonal
#pragma unroll
            for (int k = 0; k < 16; k++) {
                float a = sr[k], c2 = si[k];
                sr[k] = dr[k]*a - di[k]*c2;
                si[k] = dr[k]*c2 + di[k]*a;
            }

            // fixed Ry(theta) on all 4 qubits
            applyRyFixed<8>(sr, si, rc, rs);
            applyRyFixed<4>(sr, si, rc, rs);
            applyRyFixed<2>(sr, si, rc, rs);
            applyRyFixed<1>(sr, si, rc, rs);

            // probabilities -> 4 Z expectations
            float e0 = 0.f, e1 = 0.f, e2 = 0.f, e3 = 0.f;
#pragma unroll
            for (int k = 0; k < 16; k++) {
                float p = sr[k]*sr[k] + si[k]*si[k];
                e0 += (k & 8) ? -p : p;
                e1 += (k & 4) ? -p : p;
                e2 += (k & 2) ? -p : p;
                e3 += (k & 1) ? -p : p;
            }

            // fused fc1 accumulation: h1[o] += sum_z e[z] * W1[o, win*4+z]
            const float* wp = fc1_w + win * 4;
#pragma unroll
            for (int o = 0; o < 20; o++) {
                float4 wq = __ldg(reinterpret_cast<const float4*>(wp + o * 784));
                h1[o] = fmaf(e0, wq.x, fmaf(e1, wq.y, fmaf(e2, wq.z, fmaf(e3, wq.w, h1[o]))));
            }
        }
    }

    // fc1 bias + leaky relu + fc2
    float o0 = fc2_b[0], o1 = fc2_b[1];
#pragma unroll
    for (int o = 0; o < 20; o++) {
        float hh = h1[o] + fc1_b[o];
        hh = hh > 0.f ? hh : 0.1f * hh;
        o0 = fmaf(fc2_w[o],      hh, o0);
        o1 = fmaf(fc2_w[20 + o], hh, o1);
    }
    out[2 * b + 0] = o0;
    out[2 * b + 1] = o1;
}

extern "C" void kernel_launch(void* const* d_in, const int* in_sizes, int n_in,
                              void* d_out, int out_size) {
    const float* x     = (const float*)d_in[0];
    const float* crz   = (const float*)d_in[1];
    const float* ry    = (const float*)d_in[2];
    const float* fc1_w = (const float*)d_in[3];
    const float* fc1_b = (const float*)d_in[4];
    const float* fc2_w = (const float*)d_in[5];
    const float* fc2_b = (const float*)d_in[6];
    float* out = (float*)d_out;

    int nB = in_sizes[0] / 784;          // 16384
    const int TPB = 64;
    int blocks = (nB + TPB - 1) / TPB;   // 256 blocks -> spread over all SMs

    multi_encoding_kernel<<<blocks, TPB>>>(x, crz, ry, fc1_w, fc1_b, fc2_w, fc2_b, out, nB);
}

// round 6
// speedup vs baseline: 1.0025x; 1.0025x over previous
#include <cuda_runtime.h>

typedef unsigned long long ull;

// ---------------- f32x2 helpers (sm_103a packed fp32) ----------------
__device__ __forceinline__ ull pk2(float lo, float hi) {
    ull r;
    asm("mov.b64 %0, {%1, %2};" : "=l"(r) : "r"(__float_as_uint(lo)), "r"(__float_as_uint(hi)));
    return r;
}
__device__ __forceinline__ ull bc2(float x) { return pk2(x, x); }
__device__ __forceinline__ void upk2(ull v, float& lo, float& hi) {
    unsigned a, b;
    asm("mov.b64 {%0, %1}, %2;" : "=r"(a), "=r"(b) : "l"(v));
    lo = __uint_as_float(a); hi = __uint_as_float(b);
}
__device__ __forceinline__ ull sw2(ull v) {
    unsigned a, b;
    asm("mov.b64 {%0, %1}, %2;" : "=r"(a), "=r"(b) : "l"(v));
    ull r;
    asm("mov.b64 %0, {%1, %2};" : "=l"(r) : "r"(b), "r"(a));
    return r;
}
__device__ __forceinline__ ull f2fma(ull a, ull b, ull c) {
    ull d;
    asm("fma.rn.f32x2 %0, %1, %2, %3;" : "=l"(d) : "l"(a), "l"(b), "l"(c));
    return d;
}
__device__ __forceinline__ ull f2mul(ull a, ull b) {
    ull d;
    asm("mul.rn.f32x2 %0, %1, %2;" : "=l"(d) : "l"(a), "l"(b));
    return d;
}
__device__ __forceinline__ ull f2add(ull a, ull b) {
    ull d;
    asm("add.rn.f32x2 %0, %1, %2;" : "=l"(d) : "l"(a), "l"(b));
    return d;
}

// ---------------- scalar 2x2 complex gate ----------------
struct U2 {
    float r00, i00, r01, i01, r10, i10, r11, i11;
};

// U = Rz(a4) Ry(a3) Rz(a2) Ry(a1) Rz(a0) H
__device__ __forceinline__ U2 buildU5(float a0, float a1, float a2, float a3, float a4) {
    const float rh = 0.70710678118654752f;
    float c, s;
    __sincosf(0.5f * a0, &s, &c);
    float u00r = rh * c, u00i = -rh * s;
    float u01r = u00r,   u01i = u00i;
    float u10r = rh * c, u10i = rh * s;
    float u11r = -u10r,  u11i = -u10i;
    __sincosf(0.5f * a1, &s, &c);
    float n00r = c*u00r - s*u10r, n00i = c*u00i - s*u10i;
    float n01r = c*u01r - s*u11r, n01i = c*u01i - s*u11i;
    float n10r = s*u00r + c*u10r, n10i = s*u00i + c*u10i;
    float n11r = s*u01r + c*u11r, n11i = s*u01i + c*u11i;
    __sincosf(0.5f * a2, &s, &c);
    u00r = c*n00r + s*n00i; u00i = c*n00i - s*n00r;
    u01r = c*n01r + s*n01i; u01i = c*n01i - s*n01r;
    u10r = c*n10r - s*n10i; u10i = c*n10i + s*n10r;
    u11r = c*n11r - s*n11i; u11i = c*n11i + s*n11r;
    __sincosf(0.5f * a3, &s, &c);
    n00r = c*u00r - s*u10r; n00i = c*u00i - s*u10i;
    n01r = c*u01r - s*u11r; n01i = c*u01i - s*u11i;
    n10r = s*u00r + c*u10r; n10i = s*u00i + c*u10i;
    n11r = s*u01r + c*u11r; n11i = s*u01i + c*u11i;
    __sincosf(0.5f * a4, &s, &c);
    U2 u;
    u.r00 = c*n00r + s*n00i; u.i00 = c*n00i - s*n00r;
    u.r01 = c*n01r + s*n01i; u.i01 = c*n01i - s*n01r;
    u.r10 = c*n10r - s*n10i; u.i10 = c*n10i + s*n10r;
    u.r11 = c*n11r - s*n11i; u.i11 = c*n11i + s*n11r;
    return u;
}

// U = Rz(a)*H (last qubit)
__device__ __forceinline__ U2 buildU1(float a0) {
    const float rh = 0.70710678118654752f;
    float c, s;
    __sincosf(0.5f * a0, &s, &c);
    U2 u;
    u.r00 = rh * c;  u.i00 = -rh * s;
    u.r01 = u.r00;   u.i01 = u.i00;
    u.r10 = rh * c;  u.i10 = rh * s;
    u.r11 = -u.r10;  u.i11 = -u.i10;
    return u;
}

// ---------------- packed gate coefficients ----------------
// State packing: packed reg t holds amps (j(t), j(t)^3), j = {0,1,4,5,8,9,12,13}.
// Butterfly:  A' = cA_A * A + cA_B * B ;  B' = cB_A * A + cB_B * B (complex, per lane).
struct Upk {
    ull aar, aai, aani;   // cA_A: re, im, -im packs
    ull abr, abi, abni;   // cA_B
    ull bar, bai, bani;   // cB_A
    ull bbr, bbi, bbni;   // cB_B
};

// masks 8/4: A all-p-role, B all-q-role (broadcast coefficients)
__device__ __forceinline__ Upk packUniform(const U2& u) {
    Upk k;
    k.aar = bc2(u.r00); k.aai = bc2(u.i00); k.aani = bc2(-u.i00);
    k.abr = bc2(u.r01); k.abi = bc2(u.i01); k.abni = bc2(-u.i01);
    k.bar = bc2(u.r10); k.bai = bc2(u.i10); k.bani = bc2(-u.i10);
    k.bbr = bc2(u.r11); k.bbi = bc2(u.i11); k.bbni = bc2(-u.i11);
    return k;
}

// masks 1 (and 2 after swapping B): lane0 roles (A=p,B=q), lane1 roles (A=q,B=p)
__device__ __forceinline__ Upk packMixed(const U2& u) {
    Upk k;
    k.aar = pk2(u.r00, u.r11); k.aai = pk2(u.i00, u.i11); k.aani = pk2(-u.i00, -u.i11);
    k.abr = pk2(u.r01, u.r10); k.abi = pk2(u.i01, u.i10); k.abni = pk2(-u.i01, -u.i10);
    k.bar = pk2(u.r10, u.r01); k.bai = pk2(u.i10, u.i01); k.bani = pk2(-u.i10, -u.i01);
    k.bbr = pk2(u.r11, u.r00); k.bbi = pk2(u.i11, u.i00); k.bbni = pk2(-u.i11, -u.i00);
    return k;
}

__device__ __forceinline__ void bfly(ull& Ar, ull& Ai, ull& Br, ull& Bi, const Upk& k) {
    ull pr = f2fma(k.abni, Bi, f2fma(k.abr, Br, f2fma(k.aani, Ai, f2mul(k.aar, Ar))));
    ull pi = f2fma(k.abi,  Br, f2fma(k.abr, Bi, f2fma(k.aai,  Ar, f2mul(k.aar, Ai))));
    ull qr = f2fma(k.bbni, Bi, f2fma(k.bbr, Br, f2fma(k.bani, Ai, f2mul(k.bar, Ar))));
    ull qi = f2fma(k.bbi,  Br, f2fma(k.bbr, Bi, f2fma(k.bai,  Ar, f2mul(k.bar, Ai))));
    Ar = pr; Ai = pi; Br = qr; Bi = qi;
}

// fixed real Ry, uniform roles: A' = cc*A - s*B ; B' = s*A + cc*B
__device__ __forceinline__ void ryU(ull& Ar, ull& Ai, ull& Br, ull& Bi,
                                    ull cc, ull sss, ull nss) {
    ull ar = f2fma(nss, Br, f2mul(cc, Ar));
    ull br = f2fma(cc,  Br, f2mul(sss, Ar));
    ull ai = f2fma(nss, Bi, f2mul(cc, Ai));
    ull bi = f2fma(cc,  Bi, f2mul(sss, Ai));
    Ar = ar; Br = br; Ai = ai; Bi = bi;
}

// fixed real Ry, mixed roles (mask1 / swapped mask2): smp=(-s,s), spm=(s,-s)
__device__ __forceinline__ void ryM(ull& Ar, ull& Ai, ull& Br, ull& Bi,
                                    ull cc, ull smp, ull spm) {
    ull ar = f2fma(smp, Br, f2mul(cc, Ar));
    ull br = f2fma(cc,  Br, f2mul(spm, Ar));
    ull ai = f2fma(smp, Bi, f2mul(cc, Ai));
    ull bi = f2fma(cc,  Bi, f2mul(spm, Ai));
    Ar = ar; Br = br; Ai = ai; Bi = bi;
}

__global__ void __launch_bounds__(64)
multi_encoding_kernel(const float* __restrict__ x,
                      const float* __restrict__ crz_theta,
                      const float* __restrict__ ry_theta,
                      const float* __restrict__ fc1_w,
                      const float* __restrict__ fc1_b,
                      const float* __restrict__ fc2_w,
                      const float* __restrict__ fc2_b,
                      float* __restrict__ out,
                      int nB)
{
    int b = blockIdx.x * blockDim.x + threadIdx.x;
    if (b >= nB) return;
    const float* img = x + b * 784;

    // ---- CRZ diagonal packed constants ----
    // S values by amp: {0:0,1:-1,2:-1,3:0,4:-1,5:-2,6:0,7:1,8:-1,9:0,10:-2,11:1,12:0,13:1,14:1,15:4}
    // Packed (j, j^3): t0(0,0) identity; t1(-1,-1); t2(-1,1); t3(-2,0); t4(-1,1);
    //                  t5(0,-2); t6(0,4); t7(1,1).
    const float thc = 0.5f * crz_theta[0];
    const float c1 = cosf(thc),        s1 = sinf(thc);
    const float c2 = cosf(2.f * thc),  s2 = sinf(2.f * thc);
    const float c4 = cosf(4.f * thc),  s4 = sinf(4.f * thc);
    const ull drA  = bc2(c1);
    const ull drB  = pk2(c2, 1.f);
    const ull drC  = pk2(1.f, c2);
    const ull drD  = pk2(1.f, c4);
    const ull diMM = pk2(-s1, -s1);  // also = ndiPP
    const ull diMP = pk2(-s1,  s1);
    const ull diPP = pk2( s1,  s1);  // also = ndiMM
    const ull ndiMP = pk2( s1, -s1);
    const ull diS3 = pk2(-s2, 0.f),  ndiS3 = pk2( s2, 0.f);
    const ull diS5 = pk2(0.f, -s2),  ndiS5 = pk2(0.f,  s2);
    const ull diS6 = pk2(0.f,  s4),  ndiS6 = pk2(0.f, -s4);

    // fixed Ry constants
    float rc, rs;
    {
        float a = 0.5f * ry_theta[0];
        rc = cosf(a); rs = sinf(a);
    }
    const ull cc  = bc2(rc);
    const ull sss = bc2(rs);
    const ull nss = bc2(-rs);
    const ull smp = pk2(-rs,  rs);
    const ull spm = pk2( rs, -rs);
    const ull MM  = bc2(-1.f);

    // ---- packed state |0000>: reg t holds amps (j, j^3) ----
    ull R[8], I[8];
#pragma unroll
    for (int t = 0; t < 8; t++) { R[t] = 0ull; I[t] = 0ull; }
    R[0] = pk2(1.f, 0.f);   // amps (0,3) = (1,0)

    float h1[20];
#pragma unroll
    for (int o = 0; o < 20; o++) h1[o] = 0.f;

    int win = 0;
    for (int iw = 0; iw < 14; iw++) {
        const float* rp = img + (iw * 2) * 28;
        for (int jw = 0; jw < 14; jw++, win++) {
            const int j = jw * 2;
            float f[16];
            // Truncated edge windows are COMPACTED row-major over h*w then
            // zero-padded (matches reference _window_idx).
            if (iw < 13 && jw < 13) {            // h=4, w=4
#pragma unroll
                for (int r = 0; r < 4; r++) {
                    float2 A = *reinterpret_cast<const float2*>(rp + r * 28 + j);
                    float2 B = *reinterpret_cast<const float2*>(rp + r * 28 + j + 2);
                    f[r*4+0] = A.x; f[r*4+1] = A.y; f[r*4+2] = B.x; f[r*4+3] = B.y;
                }
            } else if (jw < 13) {                 // iw==13: h=2, w=4
#pragma unroll
                for (int r = 0; r < 2; r++) {
                    float2 A = *reinterpret_cast<const float2*>(rp + r * 28 + j);
                    float2 B = *reinterpret_cast<const float2*>(rp + r * 28 + j + 2);
                    f[r*4+0] = A.x; f[r*4+1] = A.y; f[r*4+2] = B.x; f[r*4+3] = B.y;
                }
#pragma unroll
                for (int k = 8; k < 16; k++) f[k] = 0.f;
            } else if (iw < 13) {                 // jw==13: h=4, w=2 (compacted)
#pragma unroll
                for (int r = 0; r < 4; r++) {
                    float2 A = *reinterpret_cast<const float2*>(rp + r * 28 + j);
                    f[r*2+0] = A.x; f[r*2+1] = A.y;
                }
#pragma unroll
                for (int k = 8; k < 16; k++) f[k] = 0.f;
            } else {                              // corner: h=2, w=2
                float2 A = *reinterpret_cast<const float2*>(rp + j);
                float2 B = *reinterpret_cast<const float2*>(rp + 28 + j);
                f[0] = A.x; f[1] = A.y; f[2] = B.x; f[3] = B.y;
#pragma unroll
                for (int k = 4; k < 16; k++) f[k] = 0.f;
            }

            // ---- qubit 0 (mask 8): uniform, pairs (t, t+4) ----
            {
                Upk k = packUniform(buildU5(f[0], f[1], f[2], f[3], f[4]));
                bfly(R[0], I[0], R[4], I[4], k);
                bfly(R[1], I[1], R[5], I[5], k);
                bfly(R[2], I[2], R[6], I[6], k);
                bfly(R[3], I[3], R[7], I[7], k);
            }
            // ---- qubit 1 (mask 4): uniform, pairs (t, t+2) ----
            {
                Upk k = packUniform(buildU5(f[5], f[6], f[7], f[8], f[9]));
                bfly(R[0], I[0], R[2], I[2], k);
                bfly(R[1], I[1], R[3], I[3], k);
                bfly(R[4], I[4], R[6], I[6], k);
                bfly(R[5], I[5], R[7], I[7], k);
            }
            // ---- qubit 2 (mask 2): lane-crossed -> swap odd reg, mixed coeffs ----
            {
                Upk k = packMixed(buildU5(f[10], f[11], f[12], f[13], f[14]));
#pragma unroll
                for (int p = 0; p < 8; p += 2) {
                    ull bsr = sw2(R[p + 1]), bsi = sw2(I[p + 1]);
                    bfly(R[p], I[p], bsr, bsi, k);
                    R[p + 1] = sw2(bsr); I[p + 1] = sw2(bsi);
                }
            }
            // ---- qubit 3 (mask 1): same-lane role-inverted -> mixed coeffs ----
            {
                Upk k = packMixed(buildU1(f[15]));
                bfly(R[0], I[0], R[1], I[1], k);
                bfly(R[2], I[2], R[3], I[3], k);
                bfly(R[4], I[4], R[5], I[5], k);
                bfly(R[6], I[6], R[7], I[7], k);
            }

            // ---- CRZ diagonal (t0 identity, skipped) ----
            {
                ull ar, ai;
#define CRZ1(T, DR, DI, NDI)                                   \
                ar = f2fma(NDI, I[T], f2mul(DR, R[T]));        \
                ai = f2fma(DI,  R[T], f2mul(DR, I[T]));        \
                R[T] = ar; I[T] = ai;
                CRZ1(1, drA, diMM, diPP)
                CRZ1(2, drA, diMP, ndiMP)
                CRZ1(3, drB, diS3, ndiS3)
                CRZ1(4, drA, diMP, ndiMP)
                CRZ1(5, drC, diS5, ndiS5)
                CRZ1(6, drD, diS6, ndiS6)
                CRZ1(7, drA, diPP, diMM)
#undef CRZ1
            }

            // ---- fixed Ry on 4 qubits ----
            ryU(R[0], I[0], R[4], I[4], cc, sss, nss);   // mask 8
            ryU(R[1], I[1], R[5], I[5], cc, sss, nss);
            ryU(R[2], I[2], R[6], I[6], cc, sss, nss);
            ryU(R[3], I[3], R[7], I[7], cc, sss, nss);
            ryU(R[0], I[0], R[2], I[2], cc, sss, nss);   // mask 4
            ryU(R[1], I[1], R[3], I[3], cc, sss, nss);
            ryU(R[4], I[4], R[6], I[6], cc, sss, nss);
            ryU(R[5], I[5], R[7], I[7], cc, sss, nss);
#pragma unroll
            for (int p = 0; p < 8; p += 2) {             // mask 2 (swap + mixed)
                ull bsr = sw2(R[p + 1]), bsi = sw2(I[p + 1]);
                ryM(R[p], I[p], bsr, bsi, cc, smp, spm);
                R[p + 1] = sw2(bsr); I[p + 1] = sw2(bsi);
            }
            ryM(R[0], I[0], R[1], I[1], cc, smp, spm);   // mask 1 (mixed)
            ryM(R[2], I[2], R[3], I[3], cc, smp, spm);
            ryM(R[4], I[4], R[5], I[5], cc, smp, spm);
            ryM(R[6], I[6], R[7], I[7], cc, smp, spm);

            // ---- probs -> 4 Z expectations (packed tree) ----
            ull p0 = f2fma(I[0], I[0], f2mul(R[0], R[0]));
            ull p1 = f2fma(I[1], I[1], f2mul(R[1], R[1]));
            ull p2 = f2fma(I[2], I[2], f2mul(R[2], R[2]));
            ull p3 = f2fma(I[3], I[3], f2mul(R[3], R[3]));
            ull p4 = f2fma(I[4], I[4], f2mul(R[4], R[4]));
            ull p5 = f2fma(I[5], I[5], f2mul(R[5], R[5]));
            ull p6 = f2fma(I[6], I[6], f2mul(R[6], R[6]));
            ull p7 = f2fma(I[7], I[7], f2mul(R[7], R[7]));
            ull P01 = f2add(p0, p1), P23 = f2add(p2, p3);
            ull P45 = f2add(p4, p5), P67 = f2add(p6, p7);
            ull SA = f2add(P01, P23), SB = f2add(P45, P67);    // e0 = h(SA)-h(SB)
            ull SC = f2add(P01, P45), SD = f2add(P23, P67);    // e1 = h(SC)-h(SD)
            ull ST = f2add(SA, SB);                            // e2 = T.lo - T.hi
            ull G01 = f2fma(MM, p1, p0), G23 = f2fma(MM, p3, p2);
            ull G45 = f2fma(MM, p5, p4), G67 = f2fma(MM, p7, p6);
            ull SG = f2add(f2add(G01, G23), f2add(G45, G67));  // e3 = G.lo - G.hi
            float alo, ahi, blo, bhi, clo, chi, dlo, dhi, tlo, thi, glo, ghi;
            upk2(SA, alo, ahi); upk2(SB, blo, bhi);
            upk2(SC, clo, chi); upk2(SD, dlo, dhi);
            upk2(ST, tlo, thi); upk2(SG, glo, ghi);
            float e0 = (alo + ahi) - (blo + bhi);
            float e1 = (clo + chi) - (dlo + dhi);
            float e2 = tlo - thi;
            float e3 = glo - ghi;

            // ---- fused fc1 accumulation ----
            const float* wp = fc1_w + win * 4;
#pragma unroll
            for (int o = 0; o < 20; o++) {
                float4 wq = __ldg(reinterpret_cast<const float4*>(wp + o * 784));
                h1[o] = fmaf(e0, wq.x, fmaf(e1, wq.y, fmaf(e2, wq.z, fmaf(e3, wq.w, h1[o]))));
            }
        }
    }

    // fc1 bias + leaky relu + fc2
    float o0 = fc2_b[0], o1 = fc2_b[1];
#pragma unroll
    for (int o = 0; o < 20; o++) {
        float hh = h1[o] + fc1_b[o];
        hh = hh > 0.f ? hh : 0.1f * hh;
        o0 = fmaf(fc2_w[o],      hh, o0);
        o1 = fmaf(fc2_w[20 + o], hh, o1);
    }
    out[2 * b + 0] = o0;
    out[2 * b + 1] = o1;
}

extern "C" void kernel_launch(void* const* d_in, const int* in_sizes, int n_in,
                              void* d_out, int out_size) {
    const float* x     = (const float*)d_in[0];
    const float* crz   = (const float*)d_in[1];
    const float* ry    = (const float*)d_in[2];
    const float* fc1_w = (const float*)d_in[3];
    const float* fc1_b = (const float*)d_in[4];
    const float* fc2_w = (const float*)d_in[5];
    const float* fc2_b = (const float*)d_in[6];
    float* out = (float*)d_out;

    int nB = in_sizes[0] / 784;          // 16384
    const int TPB = 64;
    int blocks = (nB + TPB - 1) / TPB;   // 256 blocks

    multi_encoding_kernel<<<blocks, TPB>>>(x, crz, ry, fc1_w, fc1_b, fc2_w, fc2_b, out, nB);
}

// round 7
// speedup vs baseline: 1.0913x; 1.0887x over previous
#include <cuda_runtime.h>

typedef unsigned long long ull;

// ---------------- f32x2 helpers ----------------
__device__ __forceinline__ ull pk2(float lo, float hi) {
    ull r;
    asm("mov.b64 %0, {%1, %2};" : "=l"(r) : "r"(__float_as_uint(lo)), "r"(__float_as_uint(hi)));
    return r;
}
__device__ __forceinline__ ull bc2(float x) { return pk2(x, x); }
__device__ __forceinline__ void upk2(ull v, float& lo, float& hi) {
    unsigned a, b;
    asm("mov.b64 {%0, %1}, %2;" : "=r"(a), "=r"(b) : "l"(v));
    lo = __uint_as_float(a); hi = __uint_as_float(b);
}
__device__ __forceinline__ ull sw2(ull v) {
    unsigned a, b;
    asm("mov.b64 {%0, %1}, %2;" : "=r"(a), "=r"(b) : "l"(v));
    ull r;
    asm("mov.b64 %0, {%1, %2};" : "=l"(r) : "r"(b), "r"(a));
    return r;
}
__device__ __forceinline__ ull f2fma(ull a, ull b, ull c) {
    ull d;
    asm("fma.rn.f32x2 %0, %1, %2, %3;" : "=l"(d) : "l"(a), "l"(b), "l"(c));
    return d;
}
__device__ __forceinline__ ull f2mul(ull a, ull b) {
    ull d;
    asm("mul.rn.f32x2 %0, %1, %2;" : "=l"(d) : "l"(a), "l"(b));
    return d;
}
__device__ __forceinline__ ull f2add(ull a, ull b) {
    ull d;
    asm("add.rn.f32x2 %0, %1, %2;" : "=l"(d) : "l"(a), "l"(b));
    return d;
}
__device__ __forceinline__ ull shflx(ull v)   { return __shfl_xor_sync(0xFFFFFFFFu, v, 1); }
__device__ __forceinline__ float shflxf(float v) { return __shfl_xor_sync(0xFFFFFFFFu, v, 1); }
__device__ __forceinline__ float hsum(ull v)  { float a, b; upk2(v, a, b); return a + b; }
__device__ __forceinline__ float hdif(ull v)  { float a, b; upk2(v, a, b); return a - b; }

// ---------------- scalar 2x2 complex gate ----------------
struct U2 {
    float r00, i00, r01, i01, r10, i10, r11, i11;
};

// U = Rz(a4) Ry(a3) Rz(a2) Ry(a1) Rz(a0) M0, with M0 = [[m00,m01],[m01,-m00]] (real).
// M0 = H for step 0, M0 = H*Ry(theta) afterwards (pending fixed Ry folded in).
__device__ __forceinline__ U2 buildU5(float m00, float m01,
                                      float a0, float a1, float a2, float a3, float a4) {
    float c, s;
    __sincosf(0.5f * a0, &s, &c);
    float u00r = m00 * c, u00i = -m00 * s;
    float u01r = m01 * c, u01i = -m01 * s;
    float u10r = m01 * c, u10i =  m01 * s;
    float u11r = -m00 * c, u11i = -m00 * s;
    __sincosf(0.5f * a1, &s, &c);
    float n00r = c*u00r - s*u10r, n00i = c*u00i - s*u10i;
    float n01r = c*u01r - s*u11r, n01i = c*u01i - s*u11i;
    float n10r = s*u00r + c*u10r, n10i = s*u00i + c*u10i;
    float n11r = s*u01r + c*u11r, n11i = s*u01i + c*u11i;
    __sincosf(0.5f * a2, &s, &c);
    u00r = c*n00r + s*n00i; u00i = c*n00i - s*n00r;
    u01r = c*n01r + s*n01i; u01i = c*n01i - s*n01r;
    u10r = c*n10r - s*n10i; u10i = c*n10i + s*n10r;
    u11r = c*n11r - s*n11i; u11i = c*n11i + s*n11r;
    __sincosf(0.5f * a3, &s, &c);
    n00r = c*u00r - s*u10r; n00i = c*u00i - s*u10i;
    n01r = c*u01r - s*u11r; n01i = c*u01i - s*u11i;
    n10r = s*u00r + c*u10r; n10i = s*u00i + c*u10i;
    n11r = s*u01r + c*u11r; n11i = s*u01i + c*u11i;
    __sincosf(0.5f * a4, &s, &c);
    U2 u;
    u.r00 = c*n00r + s*n00i; u.i00 = c*n00i - s*n00r;
    u.r01 = c*n01r + s*n01i; u.i01 = c*n01i - s*n01r;
    u.r10 = c*n10r - s*n10i; u.i10 = c*n10i + s*n10r;
    u.r11 = c*n11r - s*n11i; u.i11 = c*n11i + s*n11r;
    return u;
}

// U = Rz(a0) * M0 (last qubit)
__device__ __forceinline__ U2 buildU1(float m00, float m01, float a0) {
    float c, s;
    __sincosf(0.5f * a0, &s, &c);
    U2 u;
    u.r00 = m00 * c;  u.i00 = -m00 * s;
    u.r01 = m01 * c;  u.i01 = -m01 * s;
    u.r10 = m01 * c;  u.i10 =  m01 * s;
    u.r11 = -m00 * c; u.i11 = -m00 * s;
    return u;
}

// ---------------- packed gate coefficients (verified in R6) ----------------
struct Upk {
    ull aar, aai, aani;
    ull abr, abi, abni;
    ull bar, bai, bani;
    ull bbr, bbi, bbni;
};

__device__ __forceinline__ Upk packUniform(const U2& u) {
    Upk k;
    k.aar = bc2(u.r00); k.aai = bc2(u.i00); k.aani = bc2(-u.i00);
    k.abr = bc2(u.r01); k.abi = bc2(u.i01); k.abni = bc2(-u.i01);
    k.bar = bc2(u.r10); k.bai = bc2(u.i10); k.bani = bc2(-u.i10);
    k.bbr = bc2(u.r11); k.bbi = bc2(u.i11); k.bbni = bc2(-u.i11);
    return k;
}

__device__ __forceinline__ Upk packMixed(const U2& u) {
    Upk k;
    k.aar = pk2(u.r00, u.r11); k.aai = pk2(u.i00, u.i11); k.aani = pk2(-u.i00, -u.i11);
    k.abr = pk2(u.r01, u.r10); k.abi = pk2(u.i01, u.i10); k.abni = pk2(-u.i01, -u.i10);
    k.bar = pk2(u.r10, u.r01); k.bai = pk2(u.i10, u.i01); k.bani = pk2(-u.i10, -u.i01);
    k.bbr = pk2(u.r11, u.r00); k.bbi = pk2(u.i11, u.i00); k.bbni = pk2(-u.i11, -u.i00);
    return k;
}

__device__ __forceinline__ void bfly(ull& Ar, ull& Ai, ull& Br, ull& Bi, const Upk& k) {
    ull pr = f2fma(k.abni, Bi, f2fma(k.abr, Br, f2fma(k.aani, Ai, f2mul(k.aar, Ar))));
    ull pi = f2fma(k.abi,  Br, f2fma(k.abr, Bi, f2fma(k.aai,  Ar, f2mul(k.aar, Ai))));
    ull qr = f2fma(k.bbni, Bi, f2fma(k.bbr, Br, f2fma(k.bani, Ai, f2mul(k.bar, Ar))));
    ull qi = f2fma(k.bbi,  Br, f2fma(k.bbr, Bi, f2fma(k.bai,  Ar, f2mul(k.bar, Ai))));
    Ar = pr; Ai = pi; Br = qr; Bi = qi;
}

// ---------------- kernel: 2 lanes per element ----------------
// Lane half h holds amps j with bit3 == h, f32x2-packed as 4 regs:
//   t0=(0,3), t1=(1,2), t2=(4,7), t3=(5,6)  (+8 for h=1)

__global__ void __launch_bounds__(128)
multi_encoding_kernel(const float* __restrict__ x,
                      const float* __restrict__ crz_theta,
                      const float* __restrict__ ry_theta,
                      const float* __restrict__ fc1_w,
                      const float* __restrict__ fc1_b,
                      const float* __restrict__ fc2_w,
                      const float* __restrict__ fc2_b,
                      float* __restrict__ out,
                      int nB)
{
    const int t = blockIdx.x * blockDim.x + threadIdx.x;
    const int e = t >> 1;
    const int h = t & 1;
    if (e >= nB) return;
    const float* img = x + e * 784;

    const float rh = 0.70710678118654752f;

    // fixed Ry fold + rotated observables
    const float theta = ry_theta[0];
    float rc, rs;
    rc = cosf(0.5f * theta); rs = sinf(0.5f * theta);
    const float m00ry = rh * (rc + rs);
    const float m01ry = rh * (rc - rs);
    const float cth  = cosf(theta);
    const float sth2 = 2.0f * sinf(theta);

    // CRZ diagonal per-lane packed constants: diag = exp(+0.5i*theta_c*S)
    // S by amp: {0:0,1:-1,2:-1,3:0,4:-1,5:-2,6:0,7:1,8:-1,9:0,10:-2,11:1,12:0,13:1,14:1,15:4}
    const float thc = 0.5f * crz_theta[0];
    const float c1 = cosf(thc),       s1 = sinf(thc);
    const float c2 = cosf(2.f * thc), s2 = sinf(2.f * thc);
    const float c4 = cosf(4.f * thc), s4 = sinf(4.f * thc);
    ull drk[4], dik[4], ndik[4];
    if (h == 0) {
        drk[0] = pk2(1.f, 1.f);   dik[0] = pk2(0.f, 0.f);      // (0,3): S=(0,0)
        drk[1] = pk2(c1, c1);     dik[1] = pk2(-s1, -s1);      // (1,2): (-1,-1)
        drk[2] = pk2(c1, c1);     dik[2] = pk2(-s1, s1);       // (4,7): (-1,1)
        drk[3] = pk2(c2, 1.f);    dik[3] = pk2(-s2, 0.f);      // (5,6): (-2,0)
    } else {
        drk[0] = pk2(c1, c1);     dik[0] = pk2(-s1, s1);       // (8,11): (-1,1)
        drk[1] = pk2(1.f, c2);    dik[1] = pk2(0.f, -s2);      // (9,10): (0,-2)
        drk[2] = pk2(1.f, c4);    dik[2] = pk2(0.f, s4);       // (12,15): (0,4)
        drk[3] = pk2(c1, c1);     dik[3] = pk2(s1, s1);        // (13,14): (1,1)
    }
#pragma unroll
    for (int k = 0; k < 4; k++) {
        float a, b; upk2(dik[k], a, b);
        ndik[k] = pk2(-a, -b);
    }
    const ull MM = bc2(-1.f);

    // state |0000>
    ull R[4], I[4];
#pragma unroll
    for (int k = 0; k < 4; k++) { R[k] = 0ull; I[k] = 0ull; }
    R[0] = pk2(h ? 0.f : 1.f, 0.f);

    // fc1 accumulators: this lane owns outputs o = h*10 .. h*10+9
    float h1a[10];
#pragma unroll
    for (int o = 0; o < 10; o++) h1a[o] = 0.f;

    float m00 = rh, m01 = rh;   // step 0: M0 = H; afterwards H*Ry

    int win = 0;
    for (int iw = 0; iw < 14; iw++) {
        const float* rp = img + (iw * 2) * 28;
        for (int jw = 0; jw < 14; jw++, win++) {
            const int j = jw * 2;
            float f[16];
            // compacted edge windows (matches reference _window_idx)
            if (iw < 13 && jw < 13) {            // h=4, w=4
#pragma unroll
                for (int r = 0; r < 4; r++) {
                    float2 A = *reinterpret_cast<const float2*>(rp + r * 28 + j);
                    float2 B = *reinterpret_cast<const float2*>(rp + r * 28 + j + 2);
                    f[r*4+0] = A.x; f[r*4+1] = A.y; f[r*4+2] = B.x; f[r*4+3] = B.y;
                }
            } else if (jw < 13) {                 // iw==13: h=2, w=4
#pragma unroll
                for (int r = 0; r < 2; r++) {
                    float2 A = *reinterpret_cast<const float2*>(rp + r * 28 + j);
                    float2 B = *reinterpret_cast<const float2*>(rp + r * 28 + j + 2);
                    f[r*4+0] = A.x; f[r*4+1] = A.y; f[r*4+2] = B.x; f[r*4+3] = B.y;
                }
#pragma unroll
                for (int k = 8; k < 16; k++) f[k] = 0.f;
            } else if (iw < 13) {                 // jw==13: h=4, w=2 (compacted)
#pragma unroll
                for (int r = 0; r < 4; r++) {
                    float2 A = *reinterpret_cast<const float2*>(rp + r * 28 + j);
                    f[r*2+0] = A.x; f[r*2+1] = A.y;
                }
#pragma unroll
                for (int k = 8; k < 16; k++) f[k] = 0.f;
            } else {                              // corner: h=2, w=2
                float2 A = *reinterpret_cast<const float2*>(rp + j);
                float2 B = *reinterpret_cast<const float2*>(rp + 28 + j);
                f[0] = A.x; f[1] = A.y; f[2] = B.x; f[3] = B.y;
#pragma unroll
                for (int k = 4; k < 16; k++) f[k] = 0.f;
            }

            // ---- qubit 0 (mask 8): cross-lane one-sided butterfly ----
            {
                U2 u0 = buildU5(m00, m01, f[0], f[1], f[2], f[3], f[4]);
                // h0 lane (p-role): self=u00, other=u01 ; h1 lane (q-role): self=u11, other=u10
                const float csr = h ? u0.r11 : u0.r00;
                const float csi = h ? u0.i11 : u0.i00;
                const float cor = h ? u0.r10 : u0.r01;
                const float coi = h ? u0.i10 : u0.i01;
                const ull CSR = bc2(csr), CSI = bc2(csi), CNSI = bc2(-csi);
                const ull COR = bc2(cor), COI = bc2(coi), CNOI = bc2(-coi);
                ull Rp[4], Ip[4];
#pragma unroll
                for (int k = 0; k < 4; k++) { Rp[k] = shflx(R[k]); Ip[k] = shflx(I[k]); }
#pragma unroll
                for (int k = 0; k < 4; k++) {
                    ull nr = f2fma(CNOI, Ip[k], f2fma(COR, Rp[k],
                              f2fma(CNSI, I[k], f2mul(CSR, R[k]))));
                    ull ni = f2fma(COI, Rp[k], f2fma(COR, Ip[k],
                              f2fma(CSI, R[k], f2mul(CSR, I[k]))));
                    R[k] = nr; I[k] = ni;
                }
            }
            // ---- qubit 1 (mask 4): uniform, pairs (t0,t2),(t1,t3) ----
            {
                Upk k4 = packUniform(buildU5(m00, m01, f[5], f[6], f[7], f[8], f[9]));
                bfly(R[0], I[0], R[2], I[2], k4);
                bfly(R[1], I[1], R[3], I[3], k4);
            }
            // ---- qubit 2 (mask 2): swap + mixed, pairs (t0,sw t1),(t2,sw t3) ----
            {
                Upk k2 = packMixed(buildU5(m00, m01, f[10], f[11], f[12], f[13], f[14]));
                ull bsr = sw2(R[1]), bsi = sw2(I[1]);
                bfly(R[0], I[0], bsr, bsi, k2);
                R[1] = sw2(bsr); I[1] = sw2(bsi);
                bsr = sw2(R[3]); bsi = sw2(I[3]);
                bfly(R[2], I[2], bsr, bsi, k2);
                R[3] = sw2(bsr); I[3] = sw2(bsi);
            }
            // ---- qubit 3 (mask 1): mixed, pairs (t0,t1),(t2,t3) ----
            {
                Upk k1 = packMixed(buildU1(m00, m01, f[15]));
                bfly(R[0], I[0], R[1], I[1], k1);
                bfly(R[2], I[2], R[3], I[3], k1);
            }

            // ---- CRZ diagonal ----
#pragma unroll
            for (int k = 0; k < 4; k++) {
                ull nr = f2fma(ndik[k], I[k], f2mul(drk[k], R[k]));
                ull ni = f2fma(dik[k],  R[k], f2mul(drk[k], I[k]));
                R[k] = nr; I[k] = ni;
            }

            // ---- measurement: e_w = cos(th)*<Z_w> - sin(th)*<X_w> on pre-Ry state ----
            ull p0 = f2fma(I[0], I[0], f2mul(R[0], R[0]));
            ull p1 = f2fma(I[1], I[1], f2mul(R[1], R[1]));
            ull p2 = f2fma(I[2], I[2], f2mul(R[2], R[2]));
            ull p3 = f2fma(I[3], I[3], f2mul(R[3], R[3]));
            ull q01 = f2add(p0, p1), q23 = f2add(p2, p3);
            ull psum = f2add(q01, q23);
            ull z1v = f2fma(MM, q23, q01);                       // q01 - q23
            ull gv  = f2add(f2fma(MM, p1, p0), f2fma(MM, p3, p2));
            float Pm = hsum(psum);             // lane total prob
            float z2 = hdif(psum);
            float z1 = hsum(z1v);
            float z3 = hdif(gv);
            // X3 (mask1): t0*t1 + t2*t3 elementwise
            ull d3 = f2add(f2fma(I[0], I[1], f2mul(R[0], R[1])),
                           f2fma(I[2], I[3], f2mul(R[2], R[3])));
            float x3 = hsum(d3);
            // X1 (mask4): t0*t2 + t1*t3
            ull d1 = f2add(f2fma(I[0], I[2], f2mul(R[0], R[2])),
                           f2fma(I[1], I[3], f2mul(R[1], R[3])));
            float x1 = hsum(d1);
            // X2 (mask2): t0*sw(t1) + t2*sw(t3)
            ull d2 = f2add(f2fma(I[0], sw2(I[1]), f2mul(R[0], sw2(R[1]))),
                           f2fma(I[2], sw2(I[3]), f2mul(R[2], sw2(R[3]))));
            float x2 = hsum(d2);
            // X0 (mask8): cross-lane products (complete in each lane)
            ull Rp0 = shflx(R[0]), Ip0 = shflx(I[0]);
            ull Rp1 = shflx(R[1]), Ip1 = shflx(I[1]);
            ull Rp2 = shflx(R[2]), Ip2 = shflx(I[2]);
            ull Rp3 = shflx(R[3]), Ip3 = shflx(I[3]);
            ull d0 = f2add(f2add(f2fma(I[0], Ip0, f2mul(R[0], Rp0)),
                                 f2fma(I[1], Ip1, f2mul(R[1], Rp1))),
                           f2add(f2fma(I[2], Ip2, f2mul(R[2], Rp2)),
                                 f2fma(I[3], Ip3, f2mul(R[3], Rp3))));
            float x0 = hsum(d0);
            // exchange partials with partner lane
            float oP  = shflxf(Pm);
            float oz1 = shflxf(z1);
            float oz2 = shflxf(z2);
            float oz3 = shflxf(z3);
            float ox1 = shflxf(x1);
            float ox2 = shflxf(x2);
            float ox3 = shflxf(x3);
            float Z0 = h ? (oP - Pm) : (Pm - oP);
            float Z1 = z1 + oz1, Z2 = z2 + oz2, Z3 = z3 + oz3;
            float X1 = x1 + ox1, X2 = x2 + ox2, X3 = x3 + ox3;
            float e0 = cth * Z0 - sth2 * x0;
            float e1 = cth * Z1 - sth2 * X1;
            float e2 = cth * Z2 - sth2 * X2;
            float e3 = cth * Z3 - sth2 * X3;

            // ---- fc1 accumulation: this lane's 10 output rows ----
            const float* wp = fc1_w + (h * 10) * 784 + win * 4;
#pragma unroll
            for (int o = 0; o < 10; o++) {
                float4 wq = __ldg(reinterpret_cast<const float4*>(wp + o * 784));
                h1a[o] = fmaf(e0, wq.x, fmaf(e1, wq.y, fmaf(e2, wq.z, fmaf(e3, wq.w, h1a[o]))));
            }

            // pending fixed Ry for next step
            m00 = m00ry; m01 = m01ry;
        }
    }

    // ---- epilogue: bias + leaky relu + fc2 (split across lane pair) ----
    float a0p = 0.f, a1p = 0.f;
    const int ob = h * 10;
#pragma unroll
    for (int o = 0; o < 10; o++) {
        float hh = h1a[o] + fc1_b[ob + o];
        hh = hh > 0.f ? hh : 0.1f * hh;
        a0p = fmaf(fc2_w[ob + o],      hh, a0p);
        a1p = fmaf(fc2_w[20 + ob + o], hh, a1p);
    }
    float a0t = a0p + shflxf(a0p);
    float a1t = a1p + shflxf(a1p);
    if (h == 0) {
        out[2 * e + 0] = a0t + fc2_b[0];
        out[2 * e + 1] = a1t + fc2_b[1];
    }
}

extern "C" void kernel_launch(void* const* d_in, const int* in_sizes, int n_in,
                              void* d_out, int out_size) {
    const float* x     = (const float*)d_in[0];
    const float* crz   = (const float*)d_in[1];
    const float* ry    = (const float*)d_in[2];
    const float* fc1_w = (const float*)d_in[3];
    const float* fc1_b = (const float*)d_in[4];
    const float* fc2_w = (const float*)d_in[5];
    const float* fc2_b = (const float*)d_in[6];
    float* out = (float*)d_out;

    int nB = in_sizes[0] / 784;              // 16384
    int nThreads = nB * 2;                   // 2 lanes per element
    const int TPB = 128;
    int blocks = (nThreads + TPB - 1) / TPB; // 512 blocks -> 1024 warps

    multi_encoding_kernel<<<blocks, TPB>>>(x, crz, ry, fc1_w, fc1_b, fc2_w, fc2_b, out, nB);
}

// round 9
// speedup vs baseline: 1.1194x; 1.0257x over previous
#include <cuda_runtime.h>

typedef unsigned long long ull;

// ---------------- f32x2 helpers ----------------
__device__ __forceinline__ ull pk2(float lo, float hi) {
    ull r;
    asm("mov.b64 %0, {%1, %2};" : "=l"(r) : "r"(__float_as_uint(lo)), "r"(__float_as_uint(hi)));
    return r;
}
__device__ __forceinline__ ull bc2(float x) { return pk2(x, x); }
__device__ __forceinline__ void upk2(ull v, float& lo, float& hi) {
    unsigned a, b;
    asm("mov.b64 {%0, %1}, %2;" : "=r"(a), "=r"(b) : "l"(v));
    lo = __uint_as_float(a); hi = __uint_as_float(b);
}
__device__ __forceinline__ ull sw2(ull v) {
    unsigned a, b;
    asm("mov.b64 {%0, %1}, %2;" : "=r"(a), "=r"(b) : "l"(v));
    ull r;
    asm("mov.b64 %0, {%1, %2};" : "=l"(r) : "r"(b), "r"(a));
    return r;
}
__device__ __forceinline__ ull f2fma(ull a, ull b, ull c) {
    ull d;
    asm("fma.rn.f32x2 %0, %1, %2, %3;" : "=l"(d) : "l"(a), "l"(b), "l"(c));
    return d;
}
__device__ __forceinline__ ull f2mul(ull a, ull b) {
    ull d;
    asm("mul.rn.f32x2 %0, %1, %2;" : "=l"(d) : "l"(a), "l"(b));
    return d;
}
__device__ __forceinline__ ull f2add(ull a, ull b) {
    ull d;
    asm("add.rn.f32x2 %0, %1, %2;" : "=l"(d) : "l"(a), "l"(b));
    return d;
}
__device__ __forceinline__ ull shx(ull v, int m)  { return __shfl_xor_sync(0xFFFFFFFFu, v, m); }
__device__ __forceinline__ ull sh4(ull v, int s)  { return __shfl_sync(0xFFFFFFFFu, v, s, 4); }
__device__ __forceinline__ float hsum(ull v) { float a, b; upk2(v, a, b); return a + b; }
__device__ __forceinline__ float hdif(ull v) { float a, b; upk2(v, a, b); return a - b; }

// Top row of U = Rz(a4) Ry(a3) Rz(a2) Ry(a1) Rz(a0) M0, M0=[[m00,m01],[m01,-m00]].
// Full U recoverable: det(U)=-1 -> u10=conj(u01), u11=-conj(u00).
__device__ __forceinline__ void buildTop(float m00, float m01,
                                         float a0, float a1, float a2, float a3, float a4,
                                         float& r00, float& i00, float& r01, float& i01) {
    float c, s;
    __sincosf(0.5f * a0, &s, &c);
    float u00r = m00 * c,  u00i = -m00 * s;
    float u01r = m01 * c,  u01i = -m01 * s;
    float u10r = m01 * c,  u10i =  m01 * s;
    float u11r = -m00 * c, u11i = -m00 * s;
    __sincosf(0.5f * a1, &s, &c);
    float n00r = c*u00r - s*u10r, n00i = c*u00i - s*u10i;
    float n01r = c*u01r - s*u11r, n01i = c*u01i - s*u11i;
    float n10r = s*u00r + c*u10r, n10i = s*u00i + c*u10i;
    float n11r = s*u01r + c*u11r, n11i = s*u01i + c*u11i;
    __sincosf(0.5f * a2, &s, &c);
    u00r = c*n00r + s*n00i; u00i = c*n00i - s*n00r;
    u01r = c*n01r + s*n01i; u01i = c*n01i - s*n01r;
    u10r = c*n10r - s*n10i; u10i = c*n10i + s*n10r;
    u11r = c*n11r - s*n11i; u11i = c*n11i + s*n11r;
    __sincosf(0.5f * a3, &s, &c);
    n00r = c*u00r - s*u10r; n00i = c*u00i - s*u10i;
    n01r = c*u01r - s*u11r; n01i = c*u01i - s*u11i;
    __sincosf(0.5f * a4, &s, &c);
    r00 = c*n00r + s*n00i; i00 = c*n00i - s*n00r;
    r01 = c*n01r + s*n01i; i01 = c*n01i - s*n01r;
}

// ---------------- kernel: 4 lanes per element ----------------
// Lane sub holds amps with (bit3,bit2)=(sub>>1, sub&1); within lane amps by (b1,b0):
//   T0 = (A00, A11), T1 = (A01, A10)   [verified xor-3 pairing from R6/R7]

__global__ void __launch_bounds__(128, 4)
multi_encoding_kernel(const float* __restrict__ x,
                      const float* __restrict__ crz_theta,
                      const float* __restrict__ ry_theta,
                      const float* __restrict__ fc1_w,
                      const float* __restrict__ fc1_b,
                      const float* __restrict__ fc2_w,
                      const float* __restrict__ fc2_b,
                      float* __restrict__ out,
                      int nB)
{
    const int t = blockIdx.x * blockDim.x + threadIdx.x;
    const int e = t >> 2;
    const int sub = t & 3;
    if (e >= nB) return;
    const int l1 = (sub >> 1) & 1;   // amp bit3 (qubit 0)
    const int l0 = sub & 1;          // amp bit2 (qubit 1)
    const float* img = x + e * 784;

    const float rh = 0.70710678118654752f;

    // fixed Ry fold + rotated observables (R7-verified scheme)
    const float theta = ry_theta[0];
    const float rc = cosf(0.5f * theta), rs = sinf(0.5f * theta);
    const float m00ry = rh * (rc + rs);
    const float m01ry = rh * (rc - rs);
    const float cth  = cosf(theta);
    const float sth  = sinf(theta);
    const float nsin  = -sth;          // for doubled cross-lane X partials
    const float nsth2 = -2.0f * sth;   // for exact in-lane X partials
    const float cths0 = l1 ? -cth : cth;
    const float cths1 = l0 ? -cth : cth;
    const float sg1 = l1 ? -1.f : 1.f;
    const float sg0 = l0 ? -1.f : 1.f;

    // CRZ diagonal per-lane packed constants: diag = exp(i*thc*S)
    // S by amp: 0:0,1:-1,2:-1,3:0,4:-1,5:-2,6:0,7:1,8:-1,9:0,10:-2,11:1,12:0,13:1,14:1,15:4
    const float thc = 0.5f * crz_theta[0];
    const float c1 = cosf(thc),       s1 = sinf(thc);
    const float c2 = cosf(2.f * thc), s2 = sinf(2.f * thc);
    const float c4 = cosf(4.f * thc), s4 = sinf(4.f * thc);
    ull dr0, di0, ndi0, dr1, di1, ndi1;
    if (sub == 0) {        // T0=(0,3):(0,0)   T1=(1,2):(-1,-1)
        dr0 = pk2(1.f, 1.f); di0 = pk2(0.f, 0.f);   ndi0 = pk2(0.f, 0.f);
        dr1 = bc2(c1);       di1 = pk2(-s1, -s1);   ndi1 = pk2(s1, s1);
    } else if (sub == 1) { // T0=(4,7):(-1,1)  T1=(5,6):(-2,0)
        dr0 = bc2(c1);       di0 = pk2(-s1, s1);    ndi0 = pk2(s1, -s1);
        dr1 = pk2(c2, 1.f);  di1 = pk2(-s2, 0.f);   ndi1 = pk2(s2, 0.f);
    } else if (sub == 2) { // T0=(8,11):(-1,1) T1=(9,10):(0,-2)
        dr0 = bc2(c1);       di0 = pk2(-s1, s1);    ndi0 = pk2(s1, -s1);
        dr1 = pk2(1.f, c2);  di1 = pk2(0.f, -s2);   ndi1 = pk2(0.f, s2);
    } else {               // T0=(12,15):(0,4) T1=(13,14):(1,1)
        dr0 = pk2(1.f, c4);  di0 = pk2(0.f, s4);    ndi0 = pk2(0.f, -s4);
        dr1 = bc2(c1);       di1 = pk2(s1, s1);     ndi1 = pk2(-s1, -s1);
    }
    const ull MM = bc2(-1.f);

    // angle index set for this lane: k_m = 5*sub + m (lane 3: k0=15, rest invalid)
    int km[5], offF[5];
#pragma unroll
    for (int m = 0; m < 5; m++) {
        km[m] = 5 * sub + m;
        offF[m] = (km[m] >> 2) * 28 + (km[m] & 3);   // full-window mapping
    }

    // state |0000>
    ull R0 = pk2(sub == 0 ? 1.f : 0.f, 0.f), R1 = 0ull;
    ull I0 = 0ull, I1 = 0ull;

    // fc1 accumulators: this lane owns rows sub*5 .. sub*5+4
    const float* fc1base = fc1_w + (sub * 5) * 784;
    float h1a[5];
#pragma unroll
    for (int o = 0; o < 5; o++) h1a[o] = 0.f;

    float m00 = rh, m01 = rh;      // step 0: M0=H; then H*Ry
    float e0part = 0.f, e1p = 0.f, e2p = 0.f, e3p = 0.f;

    int win = 0;
    for (int iw = 0; iw < 14; iw++) {
        const float* wq = img + (iw * 2) * 28;
        for (int jw = 0; jw < 14; jw++, win++) {
            const float* wp = wq + jw * 2;
            // ---- load this lane's 5 angles (compacted edge windows) ----
            float a0, a1, a2, a3, a4;
            if (iw < 13 && jw < 13) {            // h=4,w=4: limit 16, full map
                a0 = (km[0] < 16) ? __ldg(wp + offF[0]) : 0.f;
                a1 = (km[1] < 16) ? __ldg(wp + offF[1]) : 0.f;
                a2 = (km[2] < 16) ? __ldg(wp + offF[2]) : 0.f;
                a3 = (km[3] < 16) ? __ldg(wp + offF[3]) : 0.f;
                a4 = (km[4] < 16) ? __ldg(wp + offF[4]) : 0.f;
            } else if (jw < 13) {                // iw==13: h=2,w=4: limit 8, full map
                a0 = (km[0] < 8) ? __ldg(wp + offF[0]) : 0.f;
                a1 = (km[1] < 8) ? __ldg(wp + offF[1]) : 0.f;
                a2 = (km[2] < 8) ? __ldg(wp + offF[2]) : 0.f;
                a3 = (km[3] < 8) ? __ldg(wp + offF[3]) : 0.f;
                a4 = (km[4] < 8) ? __ldg(wp + offF[4]) : 0.f;
            } else {                              // jw==13: compact map (h=4 or 2, w=2)
                const int lim = (iw < 13) ? 8 : 4;
                int oc0 = (km[0] >> 1) * 28 + (km[0] & 1);
                int oc1 = (km[1] >> 1) * 28 + (km[1] & 1);
                int oc2 = (km[2] >> 1) * 28 + (km[2] & 1);
                int oc3 = (km[3] >> 1) * 28 + (km[3] & 1);
                int oc4 = (km[4] >> 1) * 28 + (km[4] & 1);
                a0 = (km[0] < lim) ? __ldg(wp + oc0) : 0.f;
                a1 = (km[1] < lim) ? __ldg(wp + oc1) : 0.f;
                a2 = (km[2] < lim) ? __ldg(wp + oc2) : 0.f;
                a3 = (km[3] < lim) ? __ldg(wp + oc3) : 0.f;
                a4 = (km[4] < lim) ? __ldg(wp + oc4) : 0.f;
            }

            // ---- build own gate's top row (lane3: zero angles -> Rz(f15)*M0) ----
            float br00, bi00, br01, bi01;
            buildTop(m00, m01, a0, a1, a2, a3, a4, br00, bi00, br01, bi01);
            ull E0 = pk2(br00, bi00), E1 = pk2(br01, bi01);

            // ---- exchange: top rows of all 4 gates ----
            ull G00 = sh4(E0, 0), G01 = sh4(E1, 0);
            ull G10 = sh4(E0, 1), G11 = sh4(E1, 1);
            ull G20 = sh4(E0, 2), G21 = sh4(E1, 2);
            ull G30 = sh4(E0, 3), G31 = sh4(E1, 3);

            // ---- qubit 0 (bit3, xor 2): shuffle state (also serves prev X0) ----
            ull Rp0 = shx(R0, 2), Rp1 = shx(R1, 2);
            ull Ip0 = shx(I0, 2), Ip1 = shx(I1, 2);

            if (win > 0) {   // complete prev window's e0, reduce, accumulate fc1
                ull d0 = f2add(f2fma(I0, Ip0, f2mul(R0, Rp0)),
                               f2fma(I1, Ip1, f2mul(R1, Rp1)));
                float e0p = fmaf(nsin, hsum(d0), e0part);
                ull E01 = pk2(e0p, e1p), E23 = pk2(e2p, e3p);
                E01 = f2add(E01, shx(E01, 1)); E23 = f2add(E23, shx(E23, 1));
                E01 = f2add(E01, shx(E01, 2)); E23 = f2add(E23, shx(E23, 2));
                float ee0, ee1, ee2, ee3;
                upk2(E01, ee0, ee1); upk2(E23, ee2, ee3);
                const float* ww = fc1base + (win - 1) * 4;
#pragma unroll
                for (int o = 0; o < 5; o++) {
                    float4 wv = __ldg(reinterpret_cast<const float4*>(ww + o * 784));
                    h1a[o] = fmaf(ee0, wv.x, fmaf(ee1, wv.y, fmaf(ee2, wv.z, fmaf(ee3, wv.w, h1a[o]))));
                }
            }

            // apply qubit-0 gate (one-sided; coeffs from lane0's top row)
            {
                float r00, i00, r01, i01;
                upk2(G00, r00, i00); upk2(G01, r01, i01);
                float csr = sg1 * r00;        // u11 = (-r00, i00)
                float coi = sg1 * i01;        // u10 = (r01, -i01)
                ull CSR = bc2(csr), CSI = bc2(i00), CNSI = bc2(-i00);
                ull COR = bc2(r01), COI = bc2(coi), CNOI = bc2(-coi);
                ull nr0 = f2fma(CNOI, Ip0, f2fma(COR, Rp0, f2fma(CNSI, I0, f2mul(CSR, R0))));
                ull ni0 = f2fma(COI, Rp0, f2fma(COR, Ip0, f2fma(CSI, R0, f2mul(CSR, I0))));
                ull nr1 = f2fma(CNOI, Ip1, f2fma(COR, Rp1, f2fma(CNSI, I1, f2mul(CSR, R1))));
                ull ni1 = f2fma(COI, Rp1, f2fma(COR, Ip1, f2fma(CSI, R1, f2mul(CSR, I1))));
                R0 = nr0; I0 = ni0; R1 = nr1; I1 = ni1;
            }
            // ---- qubit 1 (bit2, xor 1): one-sided cross-lane ----
            {
                float r00, i00, r01, i01;
                upk2(G10, r00, i00); upk2(G11, r01, i01);
                float csr = sg0 * r00;
                float coi = sg0 * i01;
                ull CSR = bc2(csr), CSI = bc2(i00), CNSI = bc2(-i00);
                ull COR = bc2(r01), COI = bc2(coi), CNOI = bc2(-coi);
                ull Rq0 = shx(R0, 1), Rq1 = shx(R1, 1);
                ull Iq0 = shx(I0, 1), Iq1 = shx(I1, 1);
                ull nr0 = f2fma(CNOI, Iq0, f2fma(COR, Rq0, f2fma(CNSI, I0, f2mul(CSR, R0))));
                ull ni0 = f2fma(COI, Rq0, f2fma(COR, Iq0, f2fma(CSI, R0, f2mul(CSR, I0))));
                ull nr1 = f2fma(CNOI, Iq1, f2fma(COR, Rq1, f2fma(CNSI, I1, f2mul(CSR, R1))));
                ull ni1 = f2fma(COI, Rq1, f2fma(COR, Iq1, f2fma(CSI, R1, f2mul(CSR, I1))));
                R0 = nr0; I0 = ni0; R1 = nr1; I1 = ni1;
            }
            // ---- qubit 2 (bit1, in-lane): A=T0, B=sw2(T1), collapsed mixed packs ----
            {
                float r00, i00, r01, i01;
                upk2(G20, r00, i00); upk2(G21, r01, i01);
                ull P1 = pk2(r00, -r00), P5 = pk2(-r00, r00);
                ull P2 = bc2(i00), P2n = bc2(-i00);
                ull P3 = bc2(r01);
                ull P4 = pk2(i01, -i01), P4n = pk2(-i01, i01);
                ull Br = sw2(R1), Bi = sw2(I1);
                ull pr = f2fma(P4n, Bi, f2fma(P3, Br, f2fma(P2n, I0, f2mul(P1, R0))));
                ull pi = f2fma(P4,  Br, f2fma(P3, Bi, f2fma(P2,  R0, f2mul(P1, I0))));
                ull qr = f2fma(P2n, Bi, f2fma(P5, Br, f2fma(P4,  I0, f2mul(P3, R0))));
                ull qi = f2fma(P2,  Br, f2fma(P5, Bi, f2fma(P4n, R0, f2mul(P3, I0))));
                R0 = pr; I0 = pi; R1 = sw2(qr); I1 = sw2(qi);
            }
            // ---- qubit 3 (bit0, in-lane): A=T0, B=T1 ----
            {
                float r00, i00, r01, i01;
                upk2(G30, r00, i00); upk2(G31, r01, i01);
                ull P1 = pk2(r00, -r00), P5 = pk2(-r00, r00);
                ull P2 = bc2(i00), P2n = bc2(-i00);
                ull P3 = bc2(r01);
                ull P4 = pk2(i01, -i01), P4n = pk2(-i01, i01);
                ull pr = f2fma(P4n, I1, f2fma(P3, R1, f2fma(P2n, I0, f2mul(P1, R0))));
                ull pi = f2fma(P4,  R1, f2fma(P3, I1, f2fma(P2,  R0, f2mul(P1, I0))));
                ull qr = f2fma(P2n, I1, f2fma(P5, R1, f2fma(P4,  I0, f2mul(P3, R0))));
                ull qi = f2fma(P2,  R1, f2fma(P5, I1, f2fma(P4n, R0, f2mul(P3, I0))));
                R0 = pr; I0 = pi; R1 = qr; I1 = qi;
            }

            // ---- CRZ diagonal ----
            {
                ull nr = f2fma(ndi0, I0, f2mul(dr0, R0));
                ull ni = f2fma(di0,  R0, f2mul(dr0, I0));
                R0 = nr; I0 = ni;
                nr = f2fma(ndi1, I1, f2mul(dr1, R1));
                ni = f2fma(di1,  R1, f2mul(dr1, I1));
                R1 = nr; I1 = ni;
            }

            // ---- measurement partials (rotated observables on pre-Ry state) ----
            {
                ull p0 = f2fma(I0, I0, f2mul(R0, R0));
                ull p1 = f2fma(I1, I1, f2mul(R1, R1));
                ull s01 = f2add(p0, p1);
                ull d01 = f2fma(MM, p1, p0);
                float Pm  = hsum(s01);
                float z2p = hdif(s01);
                float z3p = hdif(d01);
                ull x2v = f2fma(I0, sw2(I1), f2mul(R0, sw2(R1)));
                ull x3v = f2fma(I0, I1, f2mul(R0, R1));
                // X1 (xor 1 partner products; doubled over quad -> nsin factor)
                ull Rq0 = shx(R0, 1), Rq1 = shx(R1, 1);
                ull Iq0 = shx(I0, 1), Iq1 = shx(I1, 1);
                ull x1v = f2add(f2fma(I0, Iq0, f2mul(R0, Rq0)),
                                f2fma(I1, Iq1, f2mul(R1, Rq1)));
                e0part = cths0 * Pm;                       // X0 term added next iter
                e1p = fmaf(nsin,  hsum(x1v), cths1 * Pm);
                e2p = fmaf(nsth2, hsum(x2v), cth * z2p);
                e3p = fmaf(nsth2, hsum(x3v), cth * z3p);
            }

            m00 = m00ry; m01 = m01ry;   // fold fixed Ry into next step's gates
        }
    }

    // ---- tail: finish window 195 ----
    {
        ull Rp0 = shx(R0, 2), Rp1 = shx(R1, 2);
        ull Ip0 = shx(I0, 2), Ip1 = shx(I1, 2);
        ull d0 = f2add(f2fma(I0, Ip0, f2mul(R0, Rp0)),
                       f2fma(I1, Ip1, f2mul(R1, Rp1)));
        float e0p = fmaf(nsin, hsum(d0), e0part);
        ull E01 = pk2(e0p, e1p), E23 = pk2(e2p, e3p);
        E01 = f2add(E01, shx(E01, 1)); E23 = f2add(E23, shx(E23, 1));
        E01 = f2add(E01, shx(E01, 2)); E23 = f2add(E23, shx(E23, 2));
        float ee0, ee1, ee2, ee3;
        upk2(E01, ee0, ee1); upk2(E23, ee2, ee3);
        const float* ww = fc1base + 195 * 4;
#pragma unroll
        for (int o = 0; o < 5; o++) {
            float4 wv = __ldg(reinterpret_cast<const float4*>(ww + o * 784));
            h1a[o] = fmaf(ee0, wv.x, fmaf(ee1, wv.y, fmaf(ee2, wv.z, fmaf(ee3, wv.w, h1a[o]))));
        }
    }

    // ---- epilogue: bias + leaky relu + fc2, reduce over quad ----
    float a0p = 0.f, a1p = 0.f;
#pragma unroll
    for (int o = 0; o < 5; o++) {
        int oo = sub * 5 + o;
        float hh = h1a[o] + fc1_b[oo];
        hh = hh > 0.f ? hh : 0.1f * hh;
        a0p = fmaf(fc2_w[oo],      hh, a0p);
        a1p = fmaf(fc2_w[20 + oo], hh, a1p);
    }
    ull A = pk2(a0p, a1p);
    A = f2add(A, shx(A, 1));
    A = f2add(A, shx(A, 2));
    if (sub == 0) {
        float aa0, aa1;
        upk2(A, aa0, aa1);
        out[2 * e + 0] = aa0 + fc2_b[0];
        out[2 * e + 1] = aa1 + fc2_b[1];
    }
}

extern "C" void kernel_launch(void* const* d_in, const int* in_sizes, int n_in,
                              void* d_out, int out_size) {
    const float* x     = (const float*)d_in[0];
    const float* crz   = (const float*)d_in[1];
    const float* ry    = (const float*)d_in[2];
    const float* fc1_w = (const float*)d_in[3];
    const float* fc1_b = (const float*)d_in[4];
    const float* fc2_w = (const float*)d_in[5];
    const float* fc2_b = (const float*)d_in[6];
    float* out = (float*)d_out;

    int nB = in_sizes[0] / 784;              // 16384
    int nThreads = nB * 4;                   // 4 lanes per element
    const int TPB = 128;
    int blocks = (nThreads + TPB - 1) / TPB; // 512 blocks -> 2048 warps

    multi_encoding_kernel<<<blocks, TPB>>>(x, crz, ry, fc1_w, fc1_b, fc2_w, fc2_b, out, nB);
}